// round 7
// baseline (speedup 1.0000x reference)
#include <cuda_runtime.h>
#include <cuda_bf16.h>
#include <cstdint>

// ---------------- problem constants ----------------
#define TB      64          // batch
#define NCH     512         // hidden cells
#define TSTEPS  1024        // SY*SX
#define G4      2048        // 4*NCH gate columns
#define K_IH    560         // 48 + NCH
#define NCTA    128         // CTA (j,s): j=col-block (64), s=batch half (2)
#define THREADS 128         // w0,w1 = pre warps; w2,w3 = seq warps
#define HSTRIDE ((size_t)TSTEPS * NCH)  // out batch-row stride (flat [t][n] view)
#define S_SEQ   528         // smem words/col for K=512 (==16 mod 32 -> conflict-free LDS.128)
#define S_X     48          // smem words/col for K=48
#define RSLOTS  32          // CTA-private ring slots (31-step lag)

// ---------------- device scratch (static: allocation-free) ----------------
__device__ float d_G[(size_t)TSTEPS * TB * G4];        // xc_k output (x@W_ihx + bias), 512 MB
__device__ uint4 d_Hq[(size_t)TSTEPS * TB * 128];      // h: {hi2,hi2,lo2,lo2} per 4 cells, 128 MB
__device__ float d_R[(size_t)NCTA * RSLOTS * 1024];    // CTA-private pre rings, 16 MB
__device__ int   d_h_done[NCTA];

// ---------------- helpers ----------------
__device__ __forceinline__ uint32_t pack2(float e0, float e1) {   // e0 -> low half
    uint32_t d;
    asm("cvt.rn.bf16x2.f32 %0, %1, %2;" : "=r"(d) : "f"(e1), "f"(e0));
    return d;
}
__device__ __forceinline__ uint32_t lo_res(uint32_t hp, float e0, float e1) {
    float h0 = __uint_as_float(hp << 16);
    float h1 = __uint_as_float(hp & 0xFFFF0000u);
    return pack2(e0 - h0, e1 - h1);
}
__device__ __forceinline__ void mma16(float* c,
                                      uint32_t a0, uint32_t a1, uint32_t a2, uint32_t a3,
                                      uint32_t b0, uint32_t b1) {
    asm volatile(
        "mma.sync.aligned.m16n8k16.row.col.f32.bf16.bf16.f32 "
        "{%0,%1,%2,%3},{%4,%5,%6,%7},{%8,%9},{%0,%1,%2,%3};"
        : "+f"(c[0]), "+f"(c[1]), "+f"(c[2]), "+f"(c[3])
        : "r"(a0), "r"(a1), "r"(a2), "r"(a3), "r"(b0), "r"(b1));
}
__device__ __forceinline__ int ld_acq(const int* p) {
    int v;
    asm volatile("ld.acquire.gpu.global.b32 %0, [%1];" : "=r"(v) : "l"(p) : "memory");
    return v;
}
__device__ __forceinline__ void st_rel(int* p, int v) {
    asm volatile("st.release.gpu.global.b32 [%0], %1;" :: "l"(p), "r"(v) : "memory");
}
__device__ __forceinline__ float sigm(float x)  { return 1.0f / (1.0f + __expf(-x)); }
__device__ __forceinline__ float tanh_f(float x){ return 1.0f - 2.0f / (__expf(2.0f * x) + 1.0f); }

// weight pair (k0,k0+1) -> smem position (k-permuted to match A fragments)
__device__ __forceinline__ int wpos(int cl, int S, int k0) {
    int kt = k0 >> 4, r = k0 & 15;
    return cl * S + kt * 16 + (r >> 2) * 4 + ((r >> 1) & 1);
}

// ---------------- init (graph-replay safe) ----------------
__global__ void init_k() {
    int i = threadIdx.x;
    if (i < NCTA) d_h_done[i] = -1;
}

// ---------------- Xc precompute: G0[t] = bias + x_t @ W_ih[:, :48]^T ----------------
__global__ void __launch_bounds__(THREADS)
xc_k(const float* __restrict__ batch, const float* __restrict__ W_ih,
     const float* __restrict__ b_ih, const float* __restrict__ b_hh) {
    __shared__ uint32_t sw[32 * S_X];
    const int tid = threadIdx.x;
    const int lane = tid & 31, w = tid >> 5;
    const int gid = lane >> 2, tig = lane & 3;
    const int row0 = w * 16 + gid, row1 = row0 + 8;
    const int gb = blockIdx.x * 32;

    for (int idx = tid; idx < 32 * 24; idx += THREADS) {
        int cl = idx / 24, k0 = (idx - cl * 24) * 2;
        float w0 = W_ih[(size_t)(gb + cl) * K_IH + k0];
        float w1 = W_ih[(size_t)(gb + cl) * K_IH + k0 + 1];
        uint32_t hi = pack2(w0, w1);
        int pos = wpos(cl, S_X, k0);
        sw[pos] = hi; sw[pos + 2] = lo_res(hi, w0, w1);
    }
    __syncthreads();

    float bias[4][2];
#pragma unroll
    for (int nt = 0; nt < 4; nt++) {
        int g = gb + nt * 8 + tig * 2;
        bias[nt][0] = b_ih[g] + b_hh[g];
        bias[nt][1] = b_ih[g + 1] + b_hh[g + 1];
    }

    for (int us = 0; us < 64; us++) {
        const int u = blockIdx.y * 64 + us;
        const int i = u >> 5, j = u & 31;
        float acc[4][4];
#pragma unroll
        for (int nt = 0; nt < 4; nt++) {
            acc[nt][0] = bias[nt][0]; acc[nt][1] = bias[nt][1];
            acc[nt][2] = bias[nt][0]; acc[nt][3] = bias[nt][1];
        }
#pragma unroll
        for (int kt = 0; kt < 3; kt++) {       // c = kt, p = tig, q = 0..3
            float4 f0 = *(const float4*)&batch[(((size_t)row0 * 3 + kt) * 128 + i * 4 + tig) * 128 + j * 4];
            float4 f1 = *(const float4*)&batch[(((size_t)row1 * 3 + kt) * 128 + i * 4 + tig) * 128 + j * 4];
            uint32_t ah0 = pack2(f0.x, f0.y), ah2 = pack2(f0.z, f0.w);
            uint32_t ah1 = pack2(f1.x, f1.y), ah3 = pack2(f1.z, f1.w);
            uint32_t al0 = lo_res(ah0, f0.x, f0.y), al2 = lo_res(ah2, f0.z, f0.w);
            uint32_t al1 = lo_res(ah1, f1.x, f1.y), al3 = lo_res(ah3, f1.z, f1.w);
#pragma unroll
            for (int nt = 0; nt < 4; nt++) {
                const uint4 q = *(const uint4*)&sw[(nt * 8 + gid) * S_X + kt * 16 + tig * 4];
                mma16(acc[nt], ah0, ah1, ah2, ah3, q.x, q.y);
                mma16(acc[nt], ah0, ah1, ah2, ah3, q.z, q.w);
                mma16(acc[nt], al0, al1, al2, al3, q.x, q.y);
            }
        }
        float* gp = d_G + (size_t)u * TB * G4;
#pragma unroll
        for (int nt = 0; nt < 4; nt++) {
            float* p0 = gp + (size_t)row0 * G4 + gb + nt * 8 + tig * 2;
            float* p1 = gp + (size_t)row1 * G4 + gb + nt * 8 + tig * 2;
            *(float2*)p0 = make_float2(acc[nt][0], acc[nt][1]);
            *(float2*)p1 = make_float2(acc[nt][2], acc[nt][3]);
        }
    }
}

// ---------------- persistent 2D-LSTM kernel ----------------
extern __shared__ uint32_t smw[];   // [0..32*S_SEQ): W_hh block; [32*S_SEQ..): W_ihh block

__global__ void __launch_bounds__(THREADS, 1)
lstm2d_k(const float* __restrict__ W_ih, const float* __restrict__ W_hh,
         float* __restrict__ out) {
    __shared__ volatile int s_pre[2];     // pre-warp progress counters
    const int tid  = threadIdx.x;
    const int lane = tid & 31;
    const int w    = tid >> 5;
    const int gid  = lane >> 2;
    const int tig  = lane & 3;
    const int bid  = blockIdx.x;
    const int j    = bid >> 1;            // gate-col block: cols {gg*512 + 8j + c}
    const int s    = bid & 1;             // batch half: rows [32s, 32s+32)
    const int nb   = j * 8;

    // ---- load both weight blocks -> smem bf16 hi/lo quads ----
    for (int idx = tid; idx < 2 * 32 * 256; idx += THREADS) {
        const int region = idx >> 13;          // 0: W_hh, 1: W_ihh
        const int id2 = idx & 8191;
        const int cl = id2 >> 8, k0 = (id2 & 255) * 2;
        const int grow = (cl >> 3) * NCH + nb + (cl & 7);
        float w0, w1;
        if (region == 0) {
            w0 = W_hh[(size_t)grow * NCH + k0];
            w1 = W_hh[(size_t)grow * NCH + k0 + 1];
        } else {
            w0 = W_ih[(size_t)grow * K_IH + 48 + k0];
            w1 = W_ih[(size_t)grow * K_IH + 48 + k0 + 1];
        }
        uint32_t hi = pack2(w0, w1);
        int pos = wpos(cl, S_SEQ, k0) + region * 32 * S_SEQ;
        smw[pos] = hi; smw[pos + 2] = lo_res(hi, w0, w1);
    }
    if (tid == 0) { s_pre[0] = 0; s_pre[1] = 0; }
    __syncthreads();

    if (w >= 2) {
        // ================= SEQ WARPS (SMSP 2,3) =================
        const int rg   = w - 2;
        const int row0 = s * 32 + rg * 16 + gid;
        const int row1 = row0 + 8;
        const int lr0  = rg * 16 + gid;            // local ring row
        const int n0   = nb + tig * 2;
        const int f0i = lane * 4, f1i = lane * 4 + 1, f2i = lane * 4 + 2, f3i = lane * 4 + 3;
        float cst[4] = {0.f, 0.f, 0.f, 0.f};

        for (int t = 0; t < TSTEPS; t++) {
            if (t > 0) {
                const int need = t - 1;
                bool ok;
                do {
                    ok = (ld_acq(&d_h_done[f0i]) >= need) &
                         (ld_acq(&d_h_done[f1i]) >= need) &
                         (ld_acq(&d_h_done[f2i]) >= need) &
                         (ld_acq(&d_h_done[f3i]) >= need);
                } while (!__all_sync(0xffffffffu, ok));
            }

            // acc = G0[t]
            const float* gp = d_G + (size_t)t * TB * G4;
            float acc[4][4];
#pragma unroll
            for (int gg = 0; gg < 4; gg++) {
                float2 v0 = __ldcg((const float2*)(gp + (size_t)row0 * G4 + gg * NCH + n0));
                float2 v1 = __ldcg((const float2*)(gp + (size_t)row1 * G4 + gg * NCH + n0));
                acc[gg][0] = v0.x; acc[gg][1] = v0.y;
                acc[gg][2] = v1.x; acc[gg][3] = v1.y;
            }

            // + ring[t] (own CTA's pre output, intra-SM)
            if (t >= 32) {
                while (s_pre[rg] < t - 31) {}
                __threadfence_block();
                const float* rp = d_R + ((size_t)bid * RSLOTS + (t & (RSLOTS - 1))) * 1024;
#pragma unroll
                for (int gg = 0; gg < 4; gg++) {
                    float2 v0 = *(const float2*)&rp[lr0 * 32 + gg * 8 + tig * 2];
                    float2 v1 = *(const float2*)&rp[(lr0 + 8) * 32 + gg * 8 + tig * 2];
                    acc[gg][0] += v0.x; acc[gg][1] += v0.y;
                    acc[gg][2] += v1.x; acc[gg][3] += v1.y;
                }
            }

            // + h_{t-1} @ W_hh^T
            if (t > 0) {
                const uint4* pq0 = d_Hq + ((size_t)(t - 1) * TB + row0) * 128 + tig;
                const uint4* pq1 = d_Hq + ((size_t)(t - 1) * TB + row1) * 128 + tig;
#pragma unroll 4
                for (int kt = 0; kt < 32; kt++) {
                    uint4 qa0 = pq0[kt * 4];
                    uint4 qa1 = pq1[kt * 4];
#pragma unroll
                    for (int gg = 0; gg < 4; gg++) {
                        const uint4 q = *(const uint4*)&smw[(gg * 8 + gid) * S_SEQ + kt * 16 + tig * 4];
                        mma16(acc[gg], qa0.x, qa1.x, qa0.y, qa1.y, q.x, q.y);   // hi*Whi
                        mma16(acc[gg], qa0.x, qa1.x, qa0.y, qa1.y, q.z, q.w);   // hi*Wlo
                        mma16(acc[gg], qa0.z, qa1.z, qa0.w, qa1.w, q.x, q.y);   // lo*Whi
                    }
                }
            }

            // activations (i,f,g,o) + publish h
            uint32_t hp[2], lp[2];
#pragma unroll
            for (int half = 0; half < 2; half++) {
                const int pA = half * 2, pB = half * 2 + 1;
                const int bb = (half == 0) ? row0 : row1;
                float c0 = sigm(acc[1][pA]) * cst[pA] + sigm(acc[0][pA]) * tanh_f(acc[2][pA]);
                float c1 = sigm(acc[1][pB]) * cst[pB] + sigm(acc[0][pB]) * tanh_f(acc[2][pB]);
                cst[pA] = c0; cst[pB] = c1;
                float h0 = sigm(acc[3][pA]) * tanh_f(c0);
                float h1 = sigm(acc[3][pB]) * tanh_f(c1);
                *(float2*)&out[(size_t)bb * HSTRIDE + (size_t)t * NCH + n0] = make_float2(h0, h1);
                hp[half] = pack2(h0, h1);
                lp[half] = lo_res(hp[half], h0, h1);
            }
            uint32_t hp0p = __shfl_xor_sync(0xffffffffu, hp[0], 1);
            uint32_t lp0p = __shfl_xor_sync(0xffffffffu, lp[0], 1);
            uint32_t hp1p = __shfl_xor_sync(0xffffffffu, hp[1], 1);
            uint32_t lp1p = __shfl_xor_sync(0xffffffffu, lp[1], 1);
            {
                const int grp = (nb >> 2) + (tig >> 1);
                uint4 val;
                size_t rsel;
                if (tig & 1) { val = make_uint4(hp1p, hp[1], lp1p, lp[1]); rsel = row1; }
                else         { val = make_uint4(hp[0], hp0p, lp[0], lp0p); rsel = row0; }
                d_Hq[((size_t)t * TB + rsel) * 128 + grp] = val;
            }
            asm volatile("bar.sync 1, 64;" ::: "memory");   // both seq warps
            if (tid == 64) st_rel(&d_h_done[bid], t);
        }
    } else {
        // ================= PRE WARPS (SMSP 0,1): ring[u+31] = h_{u-1} @ W_ihh^T =================
        const int rg   = w;
        const int row0 = s * 32 + rg * 16 + gid;
        const int row1 = row0 + 8;
        const int lr0  = rg * 16 + gid;
        const uint32_t* smp = smw + 32 * S_SEQ;
        const int f0i = lane * 4, f1i = lane * 4 + 1, f2i = lane * 4 + 2, f3i = lane * 4 + 3;

        for (int u = 1; u <= TSTEPS - 32; u++) {
            const int need = u - 1;
            bool ok;
            do {
                ok = (ld_acq(&d_h_done[f0i]) >= need) &
                     (ld_acq(&d_h_done[f1i]) >= need) &
                     (ld_acq(&d_h_done[f2i]) >= need) &
                     (ld_acq(&d_h_done[f3i]) >= need);
            } while (!__all_sync(0xffffffffu, ok));

            float acc[4][4];
#pragma unroll
            for (int gg = 0; gg < 4; gg++) {
                acc[gg][0] = 0.f; acc[gg][1] = 0.f; acc[gg][2] = 0.f; acc[gg][3] = 0.f;
            }
            const uint4* pq0 = d_Hq + ((size_t)(u - 1) * TB + row0) * 128 + tig;
            const uint4* pq1 = d_Hq + ((size_t)(u - 1) * TB + row1) * 128 + tig;
#pragma unroll 4
            for (int kt = 0; kt < 32; kt++) {
                uint4 qa0 = pq0[kt * 4];
                uint4 qa1 = pq1[kt * 4];
#pragma unroll
                for (int gg = 0; gg < 4; gg++) {
                    const uint4 q = *(const uint4*)&smp[(gg * 8 + gid) * S_SEQ + kt * 16 + tig * 4];
                    mma16(acc[gg], qa0.x, qa1.x, qa0.y, qa1.y, q.x, q.y);
                    mma16(acc[gg], qa0.x, qa1.x, qa0.y, qa1.y, q.z, q.w);
                    mma16(acc[gg], qa0.z, qa1.z, qa0.w, qa1.w, q.x, q.y);
                }
            }

            // store to own ring slot for step u+31 (overwrite-safe: own flag >= u-1 implies
            // own seq already consumed this slot at step u-1)
            float* rp = d_R + ((size_t)bid * RSLOTS + ((u + 31) & (RSLOTS - 1))) * 1024;
#pragma unroll
            for (int gg = 0; gg < 4; gg++) {
                *(float2*)&rp[lr0 * 32 + gg * 8 + tig * 2]       = make_float2(acc[gg][0], acc[gg][1]);
                *(float2*)&rp[(lr0 + 8) * 32 + gg * 8 + tig * 2] = make_float2(acc[gg][2], acc[gg][3]);
            }
            __syncwarp();
            if (lane == 0) {
                __threadfence_block();
                s_pre[rg] = u;
            }
        }
    }
}

// ---------------- launch ----------------
extern "C" void kernel_launch(void* const* d_in, const int* in_sizes, int n_in,
                              void* d_out, int out_size) {
    const float* batch = (const float*)d_in[0];
    const float* W_ih  = (const float*)d_in[1];
    const float* W_hh  = (const float*)d_in[2];
    const float* b_ih  = (const float*)d_in[3];
    const float* b_hh  = (const float*)d_in[4];
    float* out = (float*)d_out;

    const int smem = 2 * 32 * S_SEQ * 4;   // 135168 B
    cudaFuncSetAttribute(lstm2d_k, cudaFuncAttributeMaxDynamicSharedMemorySize, smem);

    init_k<<<1, NCTA>>>();
    xc_k<<<dim3(64, 16), THREADS>>>(batch, W_ih, b_ih, b_hh);
    lstm2d_k<<<NCTA, THREADS, smem>>>(W_ih, W_hh, out);
}

// round 8
// speedup vs baseline: 1.8233x; 1.8233x over previous
#include <cuda_runtime.h>
#include <cuda_bf16.h>
#include <cstdint>

// ---------------- problem constants ----------------
#define TB      64          // batch
#define NCH     512         // hidden cells
#define TSTEPS  1024        // SY*SX
#define G4      2048        // 4*NCH gate columns
#define K_IH    560         // 48 + NCH
#define NSEQ    64          // sequential-worker CTAs (8 h-cols = 32 gate cols each)
#define NPRE    64          // pre-worker CTAs (32 contiguous gate cols each)
#define GRIDSZ  (NSEQ + NPRE)
#define THREADS 128         // 4 warps; warp w owns batch rows [16w,16w+16)
#define HSTRIDE ((size_t)TSTEPS * NCH)  // out batch-row stride (flat [t][n] view)
#define S_SEQ   528         // smem words/col for K=512 (==16 mod 32 -> conflict-free LDS.128)
#define S_X     48          // smem words/col for K=48
#define FPAD    32          // ints per flag: one 128B line each (kills LTS same-line contention)

// ---------------- device scratch (static: allocation-free) ----------------
__device__ float d_G[(size_t)TSTEPS * TB * G4];        // gate pre-activations, 512 MB
__device__ uint4 d_Hq[(size_t)TSTEPS * TB * 128];      // h: {hi2,hi2,lo2,lo2} per 4 cells, 128 MB
__device__ int   d_h_done[NSEQ * FPAD];                // padded: flag i at [i*FPAD]
__device__ int   d_g_done[NPRE * FPAD];

// ---------------- helpers ----------------
__device__ __forceinline__ uint32_t pack2(float e0, float e1) {   // e0 -> low half
    uint32_t d;
    asm("cvt.rn.bf16x2.f32 %0, %1, %2;" : "=r"(d) : "f"(e1), "f"(e0));
    return d;
}
__device__ __forceinline__ uint32_t lo_res(uint32_t hp, float e0, float e1) {
    float h0 = __uint_as_float(hp << 16);
    float h1 = __uint_as_float(hp & 0xFFFF0000u);
    return pack2(e0 - h0, e1 - h1);
}
__device__ __forceinline__ void mma16(float* c,
                                      uint32_t a0, uint32_t a1, uint32_t a2, uint32_t a3,
                                      uint32_t b0, uint32_t b1) {
    asm volatile(
        "mma.sync.aligned.m16n8k16.row.col.f32.bf16.bf16.f32 "
        "{%0,%1,%2,%3},{%4,%5,%6,%7},{%8,%9},{%0,%1,%2,%3};"
        : "+f"(c[0]), "+f"(c[1]), "+f"(c[2]), "+f"(c[3])
        : "r"(a0), "r"(a1), "r"(a2), "r"(a3), "r"(b0), "r"(b1));
}
__device__ __forceinline__ int ld_acq(const int* p) {
    int v;
    asm volatile("ld.acquire.gpu.global.b32 %0, [%1];" : "=r"(v) : "l"(p) : "memory");
    return v;
}
__device__ __forceinline__ void st_rel(int* p, int v) {
    asm volatile("st.release.gpu.global.b32 [%0], %1;" :: "l"(p), "r"(v) : "memory");
}
__device__ __forceinline__ float sigm(float x)  { return 1.0f / (1.0f + __expf(-x)); }
__device__ __forceinline__ float tanh_f(float x){ return 1.0f - 2.0f / (__expf(2.0f * x) + 1.0f); }

// weight pair (k0,k0+1) -> smem position (k-permuted to match A fragments)
__device__ __forceinline__ int wpos(int cl, int S, int k0) {
    int kt = k0 >> 4, r = k0 & 15;
    return cl * S + kt * 16 + (r >> 2) * 4 + ((r >> 1) & 1);
}

// ---------------- init (graph-replay safe) ----------------
__global__ void init_k() {
    int i = blockIdx.x * blockDim.x + threadIdx.x;
    if (i < NSEQ * FPAD) d_h_done[i] = -1;
    if (i < NPRE * FPAD) d_g_done[i] = 31;   // G[0..31] have no h part: ready after xc_k
}

// ---------------- Xc precompute: G0[t] = bias + x_t @ W_ih[:, :48]^T ----------------
__global__ void __launch_bounds__(THREADS)
xc_k(const float* __restrict__ batch, const float* __restrict__ W_ih,
     const float* __restrict__ b_ih, const float* __restrict__ b_hh) {
    __shared__ uint32_t sw[32 * S_X];
    const int tid = threadIdx.x;
    const int lane = tid & 31, w = tid >> 5;
    const int gid = lane >> 2, tig = lane & 3;
    const int row0 = w * 16 + gid, row1 = row0 + 8;
    const int gb = blockIdx.x * 32;

    for (int idx = tid; idx < 32 * 24; idx += THREADS) {
        int cl = idx / 24, k0 = (idx - cl * 24) * 2;
        float w0 = W_ih[(size_t)(gb + cl) * K_IH + k0];
        float w1 = W_ih[(size_t)(gb + cl) * K_IH + k0 + 1];
        uint32_t hi = pack2(w0, w1);
        int pos = wpos(cl, S_X, k0);
        sw[pos] = hi; sw[pos + 2] = lo_res(hi, w0, w1);
    }
    __syncthreads();

    float bias[4][2];
#pragma unroll
    for (int nt = 0; nt < 4; nt++) {
        int g = gb + nt * 8 + tig * 2;
        bias[nt][0] = b_ih[g] + b_hh[g];
        bias[nt][1] = b_ih[g + 1] + b_hh[g + 1];
    }

    for (int us = 0; us < 64; us++) {
        const int u = blockIdx.y * 64 + us;
        const int i = u >> 5, j = u & 31;
        float acc[4][4];
#pragma unroll
        for (int nt = 0; nt < 4; nt++) {
            acc[nt][0] = bias[nt][0]; acc[nt][1] = bias[nt][1];
            acc[nt][2] = bias[nt][0]; acc[nt][3] = bias[nt][1];
        }
#pragma unroll
        for (int kt = 0; kt < 3; kt++) {       // c = kt, p = tig, q = 0..3
            float4 f0 = *(const float4*)&batch[(((size_t)row0 * 3 + kt) * 128 + i * 4 + tig) * 128 + j * 4];
            float4 f1 = *(const float4*)&batch[(((size_t)row1 * 3 + kt) * 128 + i * 4 + tig) * 128 + j * 4];
            uint32_t ah0 = pack2(f0.x, f0.y), ah2 = pack2(f0.z, f0.w);
            uint32_t ah1 = pack2(f1.x, f1.y), ah3 = pack2(f1.z, f1.w);
            uint32_t al0 = lo_res(ah0, f0.x, f0.y), al2 = lo_res(ah2, f0.z, f0.w);
            uint32_t al1 = lo_res(ah1, f1.x, f1.y), al3 = lo_res(ah3, f1.z, f1.w);
#pragma unroll
            for (int nt = 0; nt < 4; nt++) {
                const uint4 q = *(const uint4*)&sw[(nt * 8 + gid) * S_X + kt * 16 + tig * 4];
                mma16(acc[nt], ah0, ah1, ah2, ah3, q.x, q.y);
                mma16(acc[nt], ah0, ah1, ah2, ah3, q.z, q.w);
                mma16(acc[nt], al0, al1, al2, al3, q.x, q.y);
            }
        }
        float* gp = d_G + (size_t)u * TB * G4;
#pragma unroll
        for (int nt = 0; nt < 4; nt++) {
            float* p0 = gp + (size_t)row0 * G4 + gb + nt * 8 + tig * 2;
            float* p1 = gp + (size_t)row1 * G4 + gb + nt * 8 + tig * 2;
            *(float2*)p0 = make_float2(acc[nt][0], acc[nt][1]);
            *(float2*)p1 = make_float2(acc[nt][2], acc[nt][3]);
        }
    }
}

// ---------------- persistent 2D-LSTM kernel ----------------
extern __shared__ uint32_t smw[];

__global__ void __launch_bounds__(THREADS, 1)
lstm2d_k(const float* __restrict__ W_ih, const float* __restrict__ W_hh,
         float* __restrict__ out) {
    const int tid  = threadIdx.x;
    const int lane = tid & 31;
    const int w    = tid >> 5;
    const int gid  = lane >> 2;
    const int tig  = lane & 3;
    const int bid  = blockIdx.x;
    const int row0 = w * 16 + gid;
    const int row1 = row0 + 8;
    const bool seq = (bid < NSEQ);

    // ---- weights (K=512) -> smem bf16 hi/lo quads. seq: W_hh; pre: W_ih[:,48:560] ----
    {
        const int nb32 = seq ? bid * 8 : (bid - NSEQ) * 32;
        for (int idx = tid; idx < 32 * 256; idx += THREADS) {
            int cl = idx >> 8, k0 = (idx & 255) * 2;
            float w0, w1;
            if (seq) {
                int grow = (cl >> 3) * NCH + nb32 + (cl & 7);
                w0 = W_hh[(size_t)grow * NCH + k0];
                w1 = W_hh[(size_t)grow * NCH + k0 + 1];
            } else {
                w0 = W_ih[(size_t)(nb32 + cl) * K_IH + 48 + k0];
                w1 = W_ih[(size_t)(nb32 + cl) * K_IH + 48 + k0 + 1];
            }
            uint32_t hi = pack2(w0, w1);
            int pos = wpos(cl, S_SEQ, k0);
            smw[pos] = hi; smw[pos + 2] = lo_res(hi, w0, w1);
        }
        __syncthreads();
    }

    if (seq) {
        // ================= SEQUENTIAL WORKER =================
        const int nb = bid * 8;
        const int n0 = nb + tig * 2;
        float cst[4] = {0.f, 0.f, 0.f, 0.f};
        const int gdep = (tid < 4) ? (tid * 16 + (bid >> 2)) * FPAD : 0;

        for (int t = 0; t < TSTEPS; t++) {
            // parallel waits: g-flags (4 producers) + h-flags (64 producers), 1 thread/flag
            if (tid < 4) { while (ld_acq(&d_g_done[gdep]) < t) {} }
            else if (tid >= 64 && t > 0) { while (ld_acq(&d_h_done[(tid - 64) * FPAD]) < t - 1) {} }
            __syncthreads();

            // accumulators = gate pre-activations G[t]
            const float* gp = d_G + (size_t)t * TB * G4;
            float acc[4][4];
#pragma unroll
            for (int gg = 0; gg < 4; gg++) {
                float2 v0 = __ldcg((const float2*)(gp + (size_t)row0 * G4 + gg * NCH + n0));
                float2 v1 = __ldcg((const float2*)(gp + (size_t)row1 * G4 + gg * NCH + n0));
                acc[gg][0] = v0.x; acc[gg][1] = v0.y;
                acc[gg][2] = v1.x; acc[gg][3] = v1.y;
            }

            if (t > 0) {
                const uint4* pq0 = d_Hq + ((size_t)(t - 1) * TB + row0) * 128 + tig;
                const uint4* pq1 = d_Hq + ((size_t)(t - 1) * TB + row1) * 128 + tig;
#pragma unroll 4
                for (int kt = 0; kt < 32; kt++) {
                    uint4 qa0 = pq0[kt * 4];
                    uint4 qa1 = pq1[kt * 4];
#pragma unroll
                    for (int gg = 0; gg < 4; gg++) {
                        const uint4 q = *(const uint4*)&smw[(gg * 8 + gid) * S_SEQ + kt * 16 + tig * 4];
                        mma16(acc[gg], qa0.x, qa1.x, qa0.y, qa1.y, q.x, q.y);   // hi*Whi
                        mma16(acc[gg], qa0.x, qa1.x, qa0.y, qa1.y, q.z, q.w);   // hi*Wlo
                        mma16(acc[gg], qa0.z, qa1.z, qa0.w, qa1.w, q.x, q.y);   // lo*Whi
                    }
                }
            }

            // activations (gate order i,f,g,o); publish h as interleaved uint4
            uint32_t hp[2], lp[2];
#pragma unroll
            for (int half = 0; half < 2; half++) {
                const int pA = half * 2, pB = half * 2 + 1;
                const int bb = (half == 0) ? row0 : row1;
                float c0 = sigm(acc[1][pA]) * cst[pA] + sigm(acc[0][pA]) * tanh_f(acc[2][pA]);
                float c1 = sigm(acc[1][pB]) * cst[pB] + sigm(acc[0][pB]) * tanh_f(acc[2][pB]);
                cst[pA] = c0; cst[pB] = c1;
                float h0 = sigm(acc[3][pA]) * tanh_f(c0);
                float h1 = sigm(acc[3][pB]) * tanh_f(c1);
                *(float2*)&out[(size_t)bb * HSTRIDE + (size_t)t * NCH + n0] = make_float2(h0, h1);
                hp[half] = pack2(h0, h1);
                lp[half] = lo_res(hp[half], h0, h1);
            }
            // pair (tig, tig^1) covers 4 consecutive n; even lane stores row0, odd row1
            uint32_t hp0p = __shfl_xor_sync(0xffffffffu, hp[0], 1);
            uint32_t lp0p = __shfl_xor_sync(0xffffffffu, lp[0], 1);
            uint32_t hp1p = __shfl_xor_sync(0xffffffffu, hp[1], 1);
            uint32_t lp1p = __shfl_xor_sync(0xffffffffu, lp[1], 1);
            {
                const int grp = (nb >> 2) + (tig >> 1);
                uint4 val;
                size_t rsel;
                if (tig & 1) { val = make_uint4(hp1p, hp[1], lp1p, lp[1]); rsel = row1; }
                else         { val = make_uint4(hp[0], hp0p, lp[0], lp0p); rsel = row0; }
                d_Hq[((size_t)t * TB + rsel) * 128 + grp] = val;
            }
            __syncthreads();
            if (tid == 0) st_rel(&d_h_done[bid * FPAD], t);
        }
    } else {
        // ================= PRE-WORKER: G[u] += h_{u-32} @ W_ihh^T =================
        const int pid = bid - NSEQ;
        const int gb  = pid * 32;

        for (int u = 32; u < TSTEPS; u++) {
            // G0[u] (from xc_k) — independent of h, load before waiting
            const float* gp = d_G + (size_t)u * TB * G4;
            float acc[4][4];
#pragma unroll
            for (int nt = 0; nt < 4; nt++) {
                float2 v0 = __ldcg((const float2*)(gp + (size_t)row0 * G4 + gb + nt * 8 + tig * 2));
                float2 v1 = __ldcg((const float2*)(gp + (size_t)row1 * G4 + gb + nt * 8 + tig * 2));
                acc[nt][0] = v0.x; acc[nt][1] = v0.y;
                acc[nt][2] = v1.x; acc[nt][3] = v1.y;
            }

            if (tid < 64) { while (ld_acq(&d_h_done[tid * FPAD]) < u - 32) {} }
            __syncthreads();

            const uint4* pq0 = d_Hq + ((size_t)(u - 32) * TB + row0) * 128 + tig;
            const uint4* pq1 = d_Hq + ((size_t)(u - 32) * TB + row1) * 128 + tig;
#pragma unroll 4
            for (int kt = 0; kt < 32; kt++) {
                uint4 qa0 = pq0[kt * 4];
                uint4 qa1 = pq1[kt * 4];
#pragma unroll
                for (int nt = 0; nt < 4; nt++) {
                    const uint4 q = *(const uint4*)&smw[(nt * 8 + gid) * S_SEQ + kt * 16 + tig * 4];
                    mma16(acc[nt], qa0.x, qa1.x, qa0.y, qa1.y, q.x, q.y);
                    mma16(acc[nt], qa0.x, qa1.x, qa0.y, qa1.y, q.z, q.w);
                    mma16(acc[nt], qa0.z, qa1.z, qa0.w, qa1.w, q.x, q.y);
                }
            }

            float* gw = d_G + (size_t)u * TB * G4;
#pragma unroll
            for (int nt = 0; nt < 4; nt++) {
                float* p0 = gw + (size_t)row0 * G4 + gb + nt * 8 + tig * 2;
                float* p1 = gw + (size_t)row1 * G4 + gb + nt * 8 + tig * 2;
                *(float2*)p0 = make_float2(acc[nt][0], acc[nt][1]);
                *(float2*)p1 = make_float2(acc[nt][2], acc[nt][3]);
            }
            __syncthreads();
            if (tid == 0) st_rel(&d_g_done[pid * FPAD], u);
        }
    }
}

// ---------------- launch ----------------
extern "C" void kernel_launch(void* const* d_in, const int* in_sizes, int n_in,
                              void* d_out, int out_size) {
    const float* batch = (const float*)d_in[0];
    const float* W_ih  = (const float*)d_in[1];
    const float* W_hh  = (const float*)d_in[2];
    const float* b_ih  = (const float*)d_in[3];
    const float* b_hh  = (const float*)d_in[4];
    float* out = (float*)d_out;

    const int smem = 32 * S_SEQ * 4;   // 67584 B
    cudaFuncSetAttribute(lstm2d_k, cudaFuncAttributeMaxDynamicSharedMemorySize, smem);

    init_k<<<8, 256>>>();
    xc_k<<<dim3(64, 16), THREADS>>>(batch, W_ih, b_ih, b_hh);
    lstm2d_k<<<GRIDSZ, THREADS, smem>>>(W_ih, W_hh, out);
}

// round 9
// speedup vs baseline: 2.4676x; 1.3534x over previous
#include <cuda_runtime.h>
#include <cuda_bf16.h>
#include <cstdint>

// ---------------- problem constants ----------------
#define TB      64          // batch
#define NCH     512         // hidden cells
#define TSTEPS  1024        // SY*SX
#define G4      2048        // 4*NCH gate columns
#define K_IH    560         // 48 + NCH
#define NSEQ    64          // sequential-worker CTAs (8 h-cols = 32 gate cols each)
#define NPRE    64          // pre-worker CTAs (32 contiguous gate cols each)
#define GRIDSZ  (NSEQ + NPRE)
#define THREADS 256         // 8 warps: wl=w&3 row-group, kh=w>>2 K-half
#define HSTRIDE ((size_t)TSTEPS * NCH)  // out batch-row stride (flat [t][n] view)
#define S_SEQ   528         // smem words/col for K=512 (==16 mod 32 -> conflict-free LDS.128)
#define S_X     48          // smem words/col for K=48
#define FPAD    32          // ints per flag: one 128B line each
#define SRED    (32 * S_SEQ)   // word offset of reduction scratch

// ---------------- device scratch (static: allocation-free) ----------------
__device__ float d_G[(size_t)TSTEPS * TB * G4];        // gate pre-activations, 512 MB
__device__ uint4 d_Hq[(size_t)TSTEPS * TB * 128];      // h: {hi2,hi2,lo2,lo2} per 4 cells
__device__ int   d_h_done[NSEQ * FPAD];
__device__ int   d_g_done[NPRE * FPAD];

// ---------------- helpers ----------------
__device__ __forceinline__ uint32_t pack2(float e0, float e1) {   // e0 -> low half
    uint32_t d;
    asm("cvt.rn.bf16x2.f32 %0, %1, %2;" : "=r"(d) : "f"(e1), "f"(e0));
    return d;
}
__device__ __forceinline__ uint32_t lo_res(uint32_t hp, float e0, float e1) {
    float h0 = __uint_as_float(hp << 16);
    float h1 = __uint_as_float(hp & 0xFFFF0000u);
    return pack2(e0 - h0, e1 - h1);
}
__device__ __forceinline__ void mma16(float* c,
                                      uint32_t a0, uint32_t a1, uint32_t a2, uint32_t a3,
                                      uint32_t b0, uint32_t b1) {
    asm volatile(
        "mma.sync.aligned.m16n8k16.row.col.f32.bf16.bf16.f32 "
        "{%0,%1,%2,%3},{%4,%5,%6,%7},{%8,%9},{%0,%1,%2,%3};"
        : "+f"(c[0]), "+f"(c[1]), "+f"(c[2]), "+f"(c[3])
        : "r"(a0), "r"(a1), "r"(a2), "r"(a3), "r"(b0), "r"(b1));
}
__device__ __forceinline__ int ld_acq(const int* p) {
    int v;
    asm volatile("ld.acquire.gpu.global.b32 %0, [%1];" : "=r"(v) : "l"(p) : "memory");
    return v;
}
__device__ __forceinline__ void st_rel(int* p, int v) {
    asm volatile("st.release.gpu.global.b32 [%0], %1;" :: "l"(p), "r"(v) : "memory");
}
__device__ __forceinline__ float sigm(float x)  { return 1.0f / (1.0f + __expf(-x)); }
__device__ __forceinline__ float tanh_f(float x){ return 1.0f - 2.0f / (__expf(2.0f * x) + 1.0f); }

__device__ __forceinline__ int wpos(int cl, int S, int k0) {
    int kt = k0 >> 4, r = k0 & 15;
    return cl * S + kt * 16 + (r >> 2) * 4 + ((r >> 1) & 1);
}

// ---------------- init (graph-replay safe) ----------------
__global__ void init_k() {
    int i = blockIdx.x * blockDim.x + threadIdx.x;
    if (i < NSEQ * FPAD) d_h_done[i] = -1;
    if (i < NPRE * FPAD) d_g_done[i] = 31;   // G[0..31] have no h part: ready after xc_k
}

// ---------------- Xc precompute: G0[t] = bias + x_t @ W_ih[:, :48]^T ----------------
__global__ void __launch_bounds__(128)
xc_k(const float* __restrict__ batch, const float* __restrict__ W_ih,
     const float* __restrict__ b_ih, const float* __restrict__ b_hh) {
    __shared__ uint32_t sw[32 * S_X];
    const int tid = threadIdx.x;
    const int lane = tid & 31, w = tid >> 5;
    const int gid = lane >> 2, tig = lane & 3;
    const int row0 = w * 16 + gid, row1 = row0 + 8;
    const int gb = blockIdx.x * 32;

    for (int idx = tid; idx < 32 * 24; idx += 128) {
        int cl = idx / 24, k0 = (idx - cl * 24) * 2;
        float w0 = W_ih[(size_t)(gb + cl) * K_IH + k0];
        float w1 = W_ih[(size_t)(gb + cl) * K_IH + k0 + 1];
        uint32_t hi = pack2(w0, w1);
        int pos = wpos(cl, S_X, k0);
        sw[pos] = hi; sw[pos + 2] = lo_res(hi, w0, w1);
    }
    __syncthreads();

    float bias[4][2];
#pragma unroll
    for (int nt = 0; nt < 4; nt++) {
        int g = gb + nt * 8 + tig * 2;
        bias[nt][0] = b_ih[g] + b_hh[g];
        bias[nt][1] = b_ih[g + 1] + b_hh[g + 1];
    }

    for (int us = 0; us < 64; us++) {
        const int u = blockIdx.y * 64 + us;
        const int i = u >> 5, j = u & 31;
        float acc[4][4];
#pragma unroll
        for (int nt = 0; nt < 4; nt++) {
            acc[nt][0] = bias[nt][0]; acc[nt][1] = bias[nt][1];
            acc[nt][2] = bias[nt][0]; acc[nt][3] = bias[nt][1];
        }
#pragma unroll
        for (int kt = 0; kt < 3; kt++) {       // c = kt, p = tig, q = 0..3
            float4 f0 = *(const float4*)&batch[(((size_t)row0 * 3 + kt) * 128 + i * 4 + tig) * 128 + j * 4];
            float4 f1 = *(const float4*)&batch[(((size_t)row1 * 3 + kt) * 128 + i * 4 + tig) * 128 + j * 4];
            uint32_t ah0 = pack2(f0.x, f0.y), ah2 = pack2(f0.z, f0.w);
            uint32_t ah1 = pack2(f1.x, f1.y), ah3 = pack2(f1.z, f1.w);
            uint32_t al0 = lo_res(ah0, f0.x, f0.y), al2 = lo_res(ah2, f0.z, f0.w);
            uint32_t al1 = lo_res(ah1, f1.x, f1.y), al3 = lo_res(ah3, f1.z, f1.w);
#pragma unroll
            for (int nt = 0; nt < 4; nt++) {
                const uint4 q = *(const uint4*)&sw[(nt * 8 + gid) * S_X + kt * 16 + tig * 4];
                mma16(acc[nt], ah0, ah1, ah2, ah3, q.x, q.y);
                mma16(acc[nt], ah0, ah1, ah2, ah3, q.z, q.w);
                mma16(acc[nt], al0, al1, al2, al3, q.x, q.y);
            }
        }
        float* gp = d_G + (size_t)u * TB * G4;
#pragma unroll
        for (int nt = 0; nt < 4; nt++) {
            float* p0 = gp + (size_t)row0 * G4 + gb + nt * 8 + tig * 2;
            float* p1 = gp + (size_t)row1 * G4 + gb + nt * 8 + tig * 2;
            *(float2*)p0 = make_float2(acc[nt][0], acc[nt][1]);
            *(float2*)p1 = make_float2(acc[nt][2], acc[nt][3]);
        }
    }
}

// ---------------- persistent 2D-LSTM kernel ----------------
extern __shared__ uint32_t smw[];   // [0, 32*S_SEQ): weights; [SRED, +2560): reduction

__global__ void __launch_bounds__(THREADS, 1)
lstm2d_k(const float* __restrict__ W_ih, const float* __restrict__ W_hh,
         float* __restrict__ out) {
    const int tid  = threadIdx.x;
    const int lane = tid & 31;
    const int w    = tid >> 5;
    const int wl   = w & 3;             // row group: batch rows [16wl, 16wl+16)
    const int kh   = w >> 2;            // K half: kt range [16kh, 16kh+16)
    const int gid  = lane >> 2;
    const int tig  = lane & 3;
    const int bid  = blockIdx.x;
    const int row0 = wl * 16 + gid;
    const int row1 = row0 + 8;
    const int ktb  = kh * 16;
    const bool seq = (bid < NSEQ);
    float* red = (float*)(smw + SRED);

    // ---- weights (K=512) -> smem bf16 hi/lo quads. seq: W_hh; pre: W_ih[:,48:560] ----
    {
        const int nb32 = seq ? bid * 8 : (bid - NSEQ) * 32;
        for (int idx = tid; idx < 32 * 256; idx += THREADS) {
            int cl = idx >> 8, k0 = (idx & 255) * 2;
            float w0, w1;
            if (seq) {
                int grow = (cl >> 3) * NCH + nb32 + (cl & 7);
                w0 = W_hh[(size_t)grow * NCH + k0];
                w1 = W_hh[(size_t)grow * NCH + k0 + 1];
            } else {
                w0 = W_ih[(size_t)(nb32 + cl) * K_IH + 48 + k0];
                w1 = W_ih[(size_t)(nb32 + cl) * K_IH + 48 + k0 + 1];
            }
            uint32_t hi = pack2(w0, w1);
            int pos = wpos(cl, S_SEQ, k0);
            smw[pos] = hi; smw[pos + 2] = lo_res(hi, w0, w1);
        }
        __syncthreads();
    }

    if (seq) {
        // ================= SEQUENTIAL WORKER =================
        const int nb = bid * 8;
        const int n0 = nb + tig * 2;
        float cst[4] = {0.f, 0.f, 0.f, 0.f};
        const int gdep = (tid < 4) ? (tid * 16 + (bid >> 2)) * FPAD : 0;

        // prologue: ga = G[0] (lower warps; xc_k done by launch order)
        float ga[4][4];
        if (kh == 0) {
            const float* gp = d_G;
#pragma unroll
            for (int gg = 0; gg < 4; gg++) {
                float2 v0 = __ldcg((const float2*)(gp + (size_t)row0 * G4 + gg * NCH + n0));
                float2 v1 = __ldcg((const float2*)(gp + (size_t)row1 * G4 + gg * NCH + n0));
                ga[gg][0] = v0.x; ga[gg][1] = v0.y; ga[gg][2] = v1.x; ga[gg][3] = v1.y;
            }
        }

        for (int t = 0; t < TSTEPS; t++) {
            const int tn = (t < TSTEPS - 1) ? t + 1 : TSTEPS - 1;
            // poll: g-flags one step AHEAD (enables G prefetch); h-flags for t-1
            if (tid < 4) { while (ld_acq(&d_g_done[gdep]) < tn) {} }
            else if (tid >= 64 && tid < 128 && t > 0) {
                while (ld_acq(&d_h_done[(tid - 64) * FPAD]) < t - 1) {}
            }
            __syncthreads();

            // acc init from held ga, then prefetch ga <- G[t+1]
            float acc[4][4];
#pragma unroll
            for (int gg = 0; gg < 4; gg++) {
#pragma unroll
                for (int i = 0; i < 4; i++) acc[gg][i] = (kh == 0) ? ga[gg][i] : 0.f;
            }
            if (kh == 0) {
                const float* gp = d_G + (size_t)tn * TB * G4;
#pragma unroll
                for (int gg = 0; gg < 4; gg++) {
                    float2 v0 = __ldcg((const float2*)(gp + (size_t)row0 * G4 + gg * NCH + n0));
                    float2 v1 = __ldcg((const float2*)(gp + (size_t)row1 * G4 + gg * NCH + n0));
                    ga[gg][0] = v0.x; ga[gg][1] = v0.y; ga[gg][2] = v1.x; ga[gg][3] = v1.y;
                }
            }

            if (t > 0) {
                // front-batched A loads (MLP 32), then mma stream
                uint4 A0[16], A1[16];
                const uint4* pq0 = d_Hq + ((size_t)(t - 1) * TB + row0) * 128 + ktb * 4 + tig;
                const uint4* pq1 = d_Hq + ((size_t)(t - 1) * TB + row1) * 128 + ktb * 4 + tig;
#pragma unroll
                for (int kt = 0; kt < 16; kt++) { A0[kt] = pq0[kt * 4]; A1[kt] = pq1[kt * 4]; }
#pragma unroll
                for (int kt = 0; kt < 16; kt++) {
#pragma unroll
                    for (int gg = 0; gg < 4; gg++) {
                        const uint4 q = *(const uint4*)&smw[(gg * 8 + gid) * S_SEQ + (ktb + kt) * 16 + tig * 4];
                        mma16(acc[gg], A0[kt].x, A1[kt].x, A0[kt].y, A1[kt].y, q.x, q.y);
                        mma16(acc[gg], A0[kt].x, A1[kt].x, A0[kt].y, A1[kt].y, q.z, q.w);
                        mma16(acc[gg], A0[kt].z, A1[kt].z, A0[kt].w, A1[kt].w, q.x, q.y);
                    }
                }
            }

            // K-half reduction: upper warps -> smem, lower warps add
            if (kh == 1) {
                float* rp = red + (wl * 32 + lane) * 20;
#pragma unroll
                for (int gg = 0; gg < 4; gg++)
                    *(float4*)(rp + gg * 4) = make_float4(acc[gg][0], acc[gg][1], acc[gg][2], acc[gg][3]);
            }
            __syncthreads();

            if (kh == 0) {
                const float* rp = red + (wl * 32 + lane) * 20;
#pragma unroll
                for (int gg = 0; gg < 4; gg++) {
                    float4 v = *(const float4*)(rp + gg * 4);
                    acc[gg][0] += v.x; acc[gg][1] += v.y; acc[gg][2] += v.z; acc[gg][3] += v.w;
                }

                // activations (i,f,g,o) + publish
                uint32_t hp[2], lp[2];
#pragma unroll
                for (int half = 0; half < 2; half++) {
                    const int pA = half * 2, pB = half * 2 + 1;
                    const int bb = (half == 0) ? row0 : row1;
                    float c0 = sigm(acc[1][pA]) * cst[pA] + sigm(acc[0][pA]) * tanh_f(acc[2][pA]);
                    float c1 = sigm(acc[1][pB]) * cst[pB] + sigm(acc[0][pB]) * tanh_f(acc[2][pB]);
                    cst[pA] = c0; cst[pB] = c1;
                    float h0 = sigm(acc[3][pA]) * tanh_f(c0);
                    float h1 = sigm(acc[3][pB]) * tanh_f(c1);
                    *(float2*)&out[(size_t)bb * HSTRIDE + (size_t)t * NCH + n0] = make_float2(h0, h1);
                    hp[half] = pack2(h0, h1);
                    lp[half] = lo_res(hp[half], h0, h1);
                }
                uint32_t hp0p = __shfl_xor_sync(0xffffffffu, hp[0], 1);
                uint32_t lp0p = __shfl_xor_sync(0xffffffffu, lp[0], 1);
                uint32_t hp1p = __shfl_xor_sync(0xffffffffu, hp[1], 1);
                uint32_t lp1p = __shfl_xor_sync(0xffffffffu, lp[1], 1);
                const int grp = (nb >> 2) + (tig >> 1);
                uint4 val; size_t rsel;
                if (tig & 1) { val = make_uint4(hp1p, hp[1], lp1p, lp[1]); rsel = row1; }
                else         { val = make_uint4(hp[0], hp0p, lp[0], lp0p); rsel = row0; }
                d_Hq[((size_t)t * TB + rsel) * 128 + grp] = val;
            }
            __syncthreads();
            if (tid == 0) st_rel(&d_h_done[bid * FPAD], t);
        }
    } else {
        // ================= PRE-WORKER: G[u] = G0[u] + h_{u-32} @ W_ihh^T =================
        const int pid = bid - NSEQ;
        const int gb  = pid * 32;

        float ga[4][4];
        if (kh == 0) {
            const float* gp = d_G + (size_t)32 * TB * G4;
#pragma unroll
            for (int nt = 0; nt < 4; nt++) {
                float2 v0 = __ldcg((const float2*)(gp + (size_t)row0 * G4 + gb + nt * 8 + tig * 2));
                float2 v1 = __ldcg((const float2*)(gp + (size_t)row1 * G4 + gb + nt * 8 + tig * 2));
                ga[nt][0] = v0.x; ga[nt][1] = v0.y; ga[nt][2] = v1.x; ga[nt][3] = v1.y;
            }
        }

        for (int u = 32; u < TSTEPS; u++) {
            const int un = (u < TSTEPS - 1) ? u + 1 : TSTEPS - 1;
            if (tid < 64) { while (ld_acq(&d_h_done[tid * FPAD]) < u - 32) {} }
            __syncthreads();

            float acc[4][4];
#pragma unroll
            for (int nt = 0; nt < 4; nt++) {
#pragma unroll
                for (int i = 0; i < 4; i++) acc[nt][i] = (kh == 0) ? ga[nt][i] : 0.f;
            }
            if (kh == 0) {   // prefetch G0[u+1] (still raw xc output: only this CTA writes it, at step u+1)
                const float* gp = d_G + (size_t)un * TB * G4;
#pragma unroll
                for (int nt = 0; nt < 4; nt++) {
                    float2 v0 = __ldcg((const float2*)(gp + (size_t)row0 * G4 + gb + nt * 8 + tig * 2));
                    float2 v1 = __ldcg((const float2*)(gp + (size_t)row1 * G4 + gb + nt * 8 + tig * 2));
                    ga[nt][0] = v0.x; ga[nt][1] = v0.y; ga[nt][2] = v1.x; ga[nt][3] = v1.y;
                }
            }

            {
                uint4 A0[16], A1[16];
                const uint4* pq0 = d_Hq + ((size_t)(u - 32) * TB + row0) * 128 + ktb * 4 + tig;
                const uint4* pq1 = d_Hq + ((size_t)(u - 32) * TB + row1) * 128 + ktb * 4 + tig;
#pragma unroll
                for (int kt = 0; kt < 16; kt++) { A0[kt] = pq0[kt * 4]; A1[kt] = pq1[kt * 4]; }
#pragma unroll
                for (int kt = 0; kt < 16; kt++) {
#pragma unroll
                    for (int nt = 0; nt < 4; nt++) {
                        const uint4 q = *(const uint4*)&smw[(nt * 8 + gid) * S_SEQ + (ktb + kt) * 16 + tig * 4];
                        mma16(acc[nt], A0[kt].x, A1[kt].x, A0[kt].y, A1[kt].y, q.x, q.y);
                        mma16(acc[nt], A0[kt].x, A1[kt].x, A0[kt].y, A1[kt].y, q.z, q.w);
                        mma16(acc[nt], A0[kt].z, A1[kt].z, A0[kt].w, A1[kt].w, q.x, q.y);
                    }
                }
            }

            if (kh == 1) {
                float* rp = red + (wl * 32 + lane) * 20;
#pragma unroll
                for (int nt = 0; nt < 4; nt++)
                    *(float4*)(rp + nt * 4) = make_float4(acc[nt][0], acc[nt][1], acc[nt][2], acc[nt][3]);
            }
            __syncthreads();

            if (kh == 0) {
                const float* rp = red + (wl * 32 + lane) * 20;
#pragma unroll
                for (int nt = 0; nt < 4; nt++) {
                    float4 v = *(const float4*)(rp + nt * 4);
                    acc[nt][0] += v.x; acc[nt][1] += v.y; acc[nt][2] += v.z; acc[nt][3] += v.w;
                }
                float* gw = d_G + (size_t)u * TB * G4;
#pragma unroll
                for (int nt = 0; nt < 4; nt++) {
                    float* p0 = gw + (size_t)row0 * G4 + gb + nt * 8 + tig * 2;
                    float* p1 = gw + (size_t)row1 * G4 + gb + nt * 8 + tig * 2;
                    *(float2*)p0 = make_float2(acc[nt][0], acc[nt][1]);
                    *(float2*)p1 = make_float2(acc[nt][2], acc[nt][3]);
                }
            }
            __syncthreads();
            if (tid == 0) st_rel(&d_g_done[pid * FPAD], u);
        }
    }
}

// ---------------- launch ----------------
extern "C" void kernel_launch(void* const* d_in, const int* in_sizes, int n_in,
                              void* d_out, int out_size) {
    const float* batch = (const float*)d_in[0];
    const float* W_ih  = (const float*)d_in[1];
    const float* W_hh  = (const float*)d_in[2];
    const float* b_ih  = (const float*)d_in[3];
    const float* b_hh  = (const float*)d_in[4];
    float* out = (float*)d_out;

    const int smem = (SRED + 4 * 32 * 20) * 4;   // 67584 + 10240 = 77824 B
    cudaFuncSetAttribute(lstm2d_k, cudaFuncAttributeMaxDynamicSharedMemorySize, smem);

    init_k<<<8, 256>>>();
    xc_k<<<dim3(64, 16), 128>>>(batch, W_ih, b_ih, b_hh);
    lstm2d_k<<<GRIDSZ, THREADS, smem>>>(W_ih, W_hh, out);
}

// round 10
// speedup vs baseline: 2.5998x; 1.0536x over previous
#include <cuda_runtime.h>
#include <cuda_bf16.h>
#include <cuda_fp16.h>
#include <cstdint>

// ---------------- problem constants ----------------
#define TB      64          // batch
#define NCH     512         // hidden cells
#define TSTEPS  1024        // SY*SX
#define G4      2048        // 4*NCH gate columns
#define K_IH    560         // 48 + NCH
#define NSEQ    64          // sequential-worker CTAs (8 h-cols = 32 gate cols each)
#define NPRE    64          // pre-worker CTAs (32 contiguous gate cols each)
#define GRIDSZ  (NSEQ + NPRE)
#define THREADS 256         // 8 warps: wl=w&3 row-group, kh=w>>2 K-half
#define HSTRIDE ((size_t)TSTEPS * NCH)  // out batch-row stride (flat [t][n] view)
#define S_W     264         // smem words/col, fp16 pairs (==8 mod 32 -> conflict-free LDS.64)
#define S_X     48          // xc_k smem words/col (bf16 quads, K=48)
#define FPAD    32          // ints per flag: one 128B line each
#define SRED    (32 * S_W)  // word offset of reduction scratch

// ---------------- device scratch (static: allocation-free) ----------------
__device__ float d_G[(size_t)TSTEPS * TB * G4];        // gate pre-activations, 512 MB
__device__ uint4 d_Hq[(size_t)TSTEPS * TB * 128];      // h fp16: {hi2,hi2,lo2,lo2} per 4 cells
__device__ int   d_h_done[NSEQ * FPAD];
__device__ int   d_g_done[NPRE * FPAD];

// ---------------- bf16 helpers (xc_k only) ----------------
__device__ __forceinline__ uint32_t pack2b(float e0, float e1) {   // e0 -> low half
    uint32_t d;
    asm("cvt.rn.bf16x2.f32 %0, %1, %2;" : "=r"(d) : "f"(e1), "f"(e0));
    return d;
}
__device__ __forceinline__ uint32_t lo_resb(uint32_t hp, float e0, float e1) {
    float h0 = __uint_as_float(hp << 16);
    float h1 = __uint_as_float(hp & 0xFFFF0000u);
    return pack2b(e0 - h0, e1 - h1);
}
__device__ __forceinline__ void mma16b(float* c,
                                       uint32_t a0, uint32_t a1, uint32_t a2, uint32_t a3,
                                       uint32_t b0, uint32_t b1) {
    asm volatile(
        "mma.sync.aligned.m16n8k16.row.col.f32.bf16.bf16.f32 "
        "{%0,%1,%2,%3},{%4,%5,%6,%7},{%8,%9},{%0,%1,%2,%3};"
        : "+f"(c[0]), "+f"(c[1]), "+f"(c[2]), "+f"(c[3])
        : "r"(a0), "r"(a1), "r"(a2), "r"(a3), "r"(b0), "r"(b1));
}

// ---------------- fp16 helpers (main kernel) ----------------
__device__ __forceinline__ uint32_t pack2h(float e0, float e1) {   // e0 -> low half
    uint32_t d;
    asm("cvt.rn.f16x2.f32 %0, %1, %2;" : "=r"(d) : "f"(e1), "f"(e0));
    return d;
}
__device__ __forceinline__ uint32_t lo_resh(uint32_t hp, float e0, float e1) {
    __half2 h = *reinterpret_cast<__half2*>(&hp);
    float h0 = __half2float(__low2half(h));
    float h1 = __half2float(__high2half(h));
    return pack2h(e0 - h0, e1 - h1);
}
__device__ __forceinline__ void mma16h(float* c,
                                       uint32_t a0, uint32_t a1, uint32_t a2, uint32_t a3,
                                       uint32_t b0, uint32_t b1) {
    asm volatile(
        "mma.sync.aligned.m16n8k16.row.col.f32.f16.f16.f32 "
        "{%0,%1,%2,%3},{%4,%5,%6,%7},{%8,%9},{%0,%1,%2,%3};"
        : "+f"(c[0]), "+f"(c[1]), "+f"(c[2]), "+f"(c[3])
        : "r"(a0), "r"(a1), "r"(a2), "r"(a3), "r"(b0), "r"(b1));
}

__device__ __forceinline__ int ld_acq(const int* p) {
    int v;
    asm volatile("ld.acquire.gpu.global.b32 %0, [%1];" : "=r"(v) : "l"(p) : "memory");
    return v;
}
__device__ __forceinline__ void st_rel(int* p, int v) {
    asm volatile("st.release.gpu.global.b32 [%0], %1;" :: "l"(p), "r"(v) : "memory");
}
__device__ __forceinline__ float sigm(float x)  { return 1.0f / (1.0f + __expf(-x)); }
__device__ __forceinline__ float tanh_f(float x){ return 1.0f - 2.0f / (__expf(2.0f * x) + 1.0f); }

// ---------------- init (graph-replay safe) ----------------
__global__ void init_k() {
    int i = blockIdx.x * blockDim.x + threadIdx.x;
    if (i < NSEQ * FPAD) d_h_done[i] = -1;
    if (i < NPRE * FPAD) d_g_done[i] = 31;   // G[0..31] have no h part: ready after xc_k
}

// ---------------- Xc precompute: G0[t] = bias + x_t @ W_ih[:, :48]^T (bf16 3-pass) ----------------
__global__ void __launch_bounds__(128)
xc_k(const float* __restrict__ batch, const float* __restrict__ W_ih,
     const float* __restrict__ b_ih, const float* __restrict__ b_hh) {
    __shared__ uint32_t sw[32 * S_X];
    const int tid = threadIdx.x;
    const int lane = tid & 31, w = tid >> 5;
    const int gid = lane >> 2, tig = lane & 3;
    const int row0 = w * 16 + gid, row1 = row0 + 8;
    const int gb = blockIdx.x * 32;

    for (int idx = tid; idx < 32 * 24; idx += 128) {
        int cl = idx / 24, k0 = (idx - cl * 24) * 2;
        float w0 = W_ih[(size_t)(gb + cl) * K_IH + k0];
        float w1 = W_ih[(size_t)(gb + cl) * K_IH + k0 + 1];
        uint32_t hi = pack2b(w0, w1);
        int kt = k0 >> 4, r = k0 & 15;
        int pos = cl * S_X + kt * 16 + (r >> 2) * 4 + ((r >> 1) & 1);
        sw[pos] = hi; sw[pos + 2] = lo_resb(hi, w0, w1);
    }
    __syncthreads();

    float bias[4][2];
#pragma unroll
    for (int nt = 0; nt < 4; nt++) {
        int g = gb + nt * 8 + tig * 2;
        bias[nt][0] = b_ih[g] + b_hh[g];
        bias[nt][1] = b_ih[g + 1] + b_hh[g + 1];
    }

    for (int us = 0; us < 64; us++) {
        const int u = blockIdx.y * 64 + us;
        const int i = u >> 5, j = u & 31;
        float acc[4][4];
#pragma unroll
        for (int nt = 0; nt < 4; nt++) {
            acc[nt][0] = bias[nt][0]; acc[nt][1] = bias[nt][1];
            acc[nt][2] = bias[nt][0]; acc[nt][3] = bias[nt][1];
        }
#pragma unroll
        for (int kt = 0; kt < 3; kt++) {       // c = kt, p = tig, q = 0..3
            float4 f0 = *(const float4*)&batch[(((size_t)row0 * 3 + kt) * 128 + i * 4 + tig) * 128 + j * 4];
            float4 f1 = *(const float4*)&batch[(((size_t)row1 * 3 + kt) * 128 + i * 4 + tig) * 128 + j * 4];
            uint32_t ah0 = pack2b(f0.x, f0.y), ah2 = pack2b(f0.z, f0.w);
            uint32_t ah1 = pack2b(f1.x, f1.y), ah3 = pack2b(f1.z, f1.w);
            uint32_t al0 = lo_resb(ah0, f0.x, f0.y), al2 = lo_resb(ah2, f0.z, f0.w);
            uint32_t al1 = lo_resb(ah1, f1.x, f1.y), al3 = lo_resb(ah3, f1.z, f1.w);
#pragma unroll
            for (int nt = 0; nt < 4; nt++) {
                const uint4 q = *(const uint4*)&sw[(nt * 8 + gid) * S_X + kt * 16 + tig * 4];
                mma16b(acc[nt], ah0, ah1, ah2, ah3, q.x, q.y);
                mma16b(acc[nt], ah0, ah1, ah2, ah3, q.z, q.w);
                mma16b(acc[nt], al0, al1, al2, al3, q.x, q.y);
            }
        }
        float* gp = d_G + (size_t)u * TB * G4;
#pragma unroll
        for (int nt = 0; nt < 4; nt++) {
            float* p0 = gp + (size_t)row0 * G4 + gb + nt * 8 + tig * 2;
            float* p1 = gp + (size_t)row1 * G4 + gb + nt * 8 + tig * 2;
            *(float2*)p0 = make_float2(acc[nt][0], acc[nt][1]);
            *(float2*)p1 = make_float2(acc[nt][2], acc[nt][3]);
        }
    }
}

// ---------------- persistent 2D-LSTM kernel (fp16 2-pass) ----------------
extern __shared__ uint32_t smw[];   // [0, 32*S_W): fp16 weights; [SRED, +2560): reduction

__global__ void __launch_bounds__(THREADS, 1)
lstm2d_k(const float* __restrict__ W_ih, const float* __restrict__ W_hh,
         float* __restrict__ out) {
    const int tid  = threadIdx.x;
    const int lane = tid & 31;
    const int w    = tid >> 5;
    const int wl   = w & 3;             // row group: batch rows [16wl, 16wl+16)
    const int kh   = w >> 2;            // K half: kt range [16kh, 16kh+16)
    const int gid  = lane >> 2;
    const int tig  = lane & 3;
    const int bid  = blockIdx.x;
    const int row0 = wl * 16 + gid;
    const int row1 = row0 + 8;
    const int ktb  = kh * 16;
    const bool seq = (bid < NSEQ);
    float* red = (float*)(smw + SRED);

    // ---- weights (K=512) -> smem fp16 pairs. seq: W_hh; pre: W_ih[:,48:560] ----
    {
        const int nb32 = seq ? bid * 8 : (bid - NSEQ) * 32;
        for (int idx = tid; idx < 32 * 256; idx += THREADS) {
            int cl = idx >> 8, k0 = (idx & 255) * 2;
            float w0, w1;
            if (seq) {
                int grow = (cl >> 3) * NCH + nb32 + (cl & 7);
                w0 = W_hh[(size_t)grow * NCH + k0];
                w1 = W_hh[(size_t)grow * NCH + k0 + 1];
            } else {
                w0 = W_ih[(size_t)(nb32 + cl) * K_IH + 48 + k0];
                w1 = W_ih[(size_t)(nb32 + cl) * K_IH + 48 + k0 + 1];
            }
            int kt = k0 >> 4, r = k0 & 15;
            smw[cl * S_W + kt * 8 + (r >> 2) * 2 + ((r >> 1) & 1)] = pack2h(w0, w1);
        }
        __syncthreads();
    }

    if (seq) {
        // ================= SEQUENTIAL WORKER =================
        const int nb = bid * 8;
        const int n0 = nb + tig * 2;
        float cst[4] = {0.f, 0.f, 0.f, 0.f};
        const int gdep = (tid < 4) ? (tid * 16 + (bid >> 2)) * FPAD : 0;

        float ga[4][4];
        if (kh == 0) {
            const float* gp = d_G;
#pragma unroll
            for (int gg = 0; gg < 4; gg++) {
                float2 v0 = __ldcg((const float2*)(gp + (size_t)row0 * G4 + gg * NCH + n0));
                float2 v1 = __ldcg((const float2*)(gp + (size_t)row1 * G4 + gg * NCH + n0));
                ga[gg][0] = v0.x; ga[gg][1] = v0.y; ga[gg][2] = v1.x; ga[gg][3] = v1.y;
            }
        }

        for (int t = 0; t < TSTEPS; t++) {
            const int tn = (t < TSTEPS - 1) ? t + 1 : TSTEPS - 1;
            // poll: g-flags one step AHEAD (enables G prefetch); h-flags for t-1
            if (tid < 4) { while (ld_acq(&d_g_done[gdep]) < tn) {} }
            else if (tid >= 64 && tid < 128 && t > 0) {
                while (ld_acq(&d_h_done[(tid - 64) * FPAD]) < t - 1) {}
            }
            __syncthreads();

            float acc[4][4];
#pragma unroll
            for (int gg = 0; gg < 4; gg++) {
#pragma unroll
                for (int i = 0; i < 4; i++) acc[gg][i] = (kh == 0) ? ga[gg][i] : 0.f;
            }
            if (kh == 0) {   // prefetch ga <- G[t+1]
                const float* gp = d_G + (size_t)tn * TB * G4;
#pragma unroll
                for (int gg = 0; gg < 4; gg++) {
                    float2 v0 = __ldcg((const float2*)(gp + (size_t)row0 * G4 + gg * NCH + n0));
                    float2 v1 = __ldcg((const float2*)(gp + (size_t)row1 * G4 + gg * NCH + n0));
                    ga[gg][0] = v0.x; ga[gg][1] = v0.y; ga[gg][2] = v1.x; ga[gg][3] = v1.y;
                }
            }

            if (t > 0) {
                uint4 A0[16], A1[16];
                const uint4* pq0 = d_Hq + ((size_t)(t - 1) * TB + row0) * 128 + ktb * 4 + tig;
                const uint4* pq1 = d_Hq + ((size_t)(t - 1) * TB + row1) * 128 + ktb * 4 + tig;
#pragma unroll
                for (int kt = 0; kt < 16; kt++) { A0[kt] = pq0[kt * 4]; A1[kt] = pq1[kt * 4]; }
#pragma unroll
                for (int kt = 0; kt < 16; kt++) {
#pragma unroll
                    for (int gg = 0; gg < 4; gg++) {
                        const uint2 q = *(const uint2*)&smw[(gg * 8 + gid) * S_W + (ktb + kt) * 8 + tig * 2];
                        mma16h(acc[gg], A0[kt].x, A1[kt].x, A0[kt].y, A1[kt].y, q.x, q.y);  // hi*W
                        mma16h(acc[gg], A0[kt].z, A1[kt].z, A0[kt].w, A1[kt].w, q.x, q.y);  // lo*W
                    }
                }
            }

            // K-half reduction: upper warps -> smem, lower warps add
            if (kh == 1) {
                float* rp = red + (wl * 32 + lane) * 20;
#pragma unroll
                for (int gg = 0; gg < 4; gg++)
                    *(float4*)(rp + gg * 4) = make_float4(acc[gg][0], acc[gg][1], acc[gg][2], acc[gg][3]);
            }
            __syncthreads();

            if (kh == 0) {
                const float* rp = red + (wl * 32 + lane) * 20;
#pragma unroll
                for (int gg = 0; gg < 4; gg++) {
                    float4 v = *(const float4*)(rp + gg * 4);
                    acc[gg][0] += v.x; acc[gg][1] += v.y; acc[gg][2] += v.z; acc[gg][3] += v.w;
                }

                // activations (i,f,g,o) + publish
                uint32_t hp[2], lp[2];
#pragma unroll
                for (int half = 0; half < 2; half++) {
                    const int pA = half * 2, pB = half * 2 + 1;
                    const int bb = (half == 0) ? row0 : row1;
                    float c0 = sigm(acc[1][pA]) * cst[pA] + sigm(acc[0][pA]) * tanh_f(acc[2][pA]);
                    float c1 = sigm(acc[1][pB]) * cst[pB] + sigm(acc[0][pB]) * tanh_f(acc[2][pB]);
                    cst[pA] = c0; cst[pB] = c1;
                    float h0 = sigm(acc[3][pA]) * tanh_f(c0);
                    float h1 = sigm(acc[3][pB]) * tanh_f(c1);
                    *(float2*)&out[(size_t)bb * HSTRIDE + (size_t)t * NCH + n0] = make_float2(h0, h1);
                    hp[half] = pack2h(h0, h1);
                    lp[half] = lo_resh(hp[half], h0, h1);
                }
                uint32_t hp0p = __shfl_xor_sync(0xffffffffu, hp[0], 1);
                uint32_t lp0p = __shfl_xor_sync(0xffffffffu, lp[0], 1);
                uint32_t hp1p = __shfl_xor_sync(0xffffffffu, hp[1], 1);
                uint32_t lp1p = __shfl_xor_sync(0xffffffffu, lp[1], 1);
                const int grp = (nb >> 2) + (tig >> 1);
                uint4 val; size_t rsel;
                if (tig & 1) { val = make_uint4(hp1p, hp[1], lp1p, lp[1]); rsel = row1; }
                else         { val = make_uint4(hp[0], hp0p, lp[0], lp0p); rsel = row0; }
                d_Hq[((size_t)t * TB + rsel) * 128 + grp] = val;
            }
            __syncthreads();
            if (tid == 0) st_rel(&d_h_done[bid * FPAD], t);
        }
    } else {
        // ================= PRE-WORKER: G[u] = G0[u] + h_{u-32} @ W_ihh^T =================
        const int pid = bid - NSEQ;
        const int gb  = pid * 32;

        float ga[4][4];
        if (kh == 0) {
            const float* gp = d_G + (size_t)32 * TB * G4;
#pragma unroll
            for (int nt = 0; nt < 4; nt++) {
                float2 v0 = __ldcg((const float2*)(gp + (size_t)row0 * G4 + gb + nt * 8 + tig * 2));
                float2 v1 = __ldcg((const float2*)(gp + (size_t)row1 * G4 + gb + nt * 8 + tig * 2));
                ga[nt][0] = v0.x; ga[nt][1] = v0.y; ga[nt][2] = v1.x; ga[nt][3] = v1.y;
            }
        }

        for (int u = 32; u < TSTEPS; u++) {
            const int un = (u < TSTEPS - 1) ? u + 1 : TSTEPS - 1;
            if (tid < 64) { while (ld_acq(&d_h_done[tid * FPAD]) < u - 32) {} }
            __syncthreads();

            float acc[4][4];
#pragma unroll
            for (int nt = 0; nt < 4; nt++) {
#pragma unroll
                for (int i = 0; i < 4; i++) acc[nt][i] = (kh == 0) ? ga[nt][i] : 0.f;
            }
            if (kh == 0) {   // prefetch G0[u+1] (raw xc output; only this CTA updates it)
                const float* gp = d_G + (size_t)un * TB * G4;
#pragma unroll
                for (int nt = 0; nt < 4; nt++) {
                    float2 v0 = __ldcg((const float2*)(gp + (size_t)row0 * G4 + gb + nt * 8 + tig * 2));
                    float2 v1 = __ldcg((const float2*)(gp + (size_t)row1 * G4 + gb + nt * 8 + tig * 2));
                    ga[nt][0] = v0.x; ga[nt][1] = v0.y; ga[nt][2] = v1.x; ga[nt][3] = v1.y;
                }
            }

            {
                uint4 A0[16], A1[16];
                const uint4* pq0 = d_Hq + ((size_t)(u - 32) * TB + row0) * 128 + ktb * 4 + tig;
                const uint4* pq1 = d_Hq + ((size_t)(u - 32) * TB + row1) * 128 + ktb * 4 + tig;
#pragma unroll
                for (int kt = 0; kt < 16; kt++) { A0[kt] = pq0[kt * 4]; A1[kt] = pq1[kt * 4]; }
#pragma unroll
                for (int kt = 0; kt < 16; kt++) {
#pragma unroll
                    for (int nt = 0; nt < 4; nt++) {
                        const uint2 q = *(const uint2*)&smw[(nt * 8 + gid) * S_W + (ktb + kt) * 8 + tig * 2];
                        mma16h(acc[nt], A0[kt].x, A1[kt].x, A0[kt].y, A1[kt].y, q.x, q.y);
                        mma16h(acc[nt], A0[kt].z, A1[kt].z, A0[kt].w, A1[kt].w, q.x, q.y);
                    }
                }
            }

            if (kh == 1) {
                float* rp = red + (wl * 32 + lane) * 20;
#pragma unroll
                for (int nt = 0; nt < 4; nt++)
                    *(float4*)(rp + nt * 4) = make_float4(acc[nt][0], acc[nt][1], acc[nt][2], acc[nt][3]);
            }
            __syncthreads();

            if (kh == 0) {
                const float* rp = red + (wl * 32 + lane) * 20;
#pragma unroll
                for (int nt = 0; nt < 4; nt++) {
                    float4 v = *(const float4*)(rp + nt * 4);
                    acc[nt][0] += v.x; acc[nt][1] += v.y; acc[nt][2] += v.z; acc[nt][3] += v.w;
                }
                float* gw = d_G + (size_t)u * TB * G4;
#pragma unroll
                for (int nt = 0; nt < 4; nt++) {
                    float* p0 = gw + (size_t)row0 * G4 + gb + nt * 8 + tig * 2;
                    float* p1 = gw + (size_t)row1 * G4 + gb + nt * 8 + tig * 2;
                    *(float2*)p0 = make_float2(acc[nt][0], acc[nt][1]);
                    *(float2*)p1 = make_float2(acc[nt][2], acc[nt][3]);
                }
            }
            __syncthreads();
            if (tid == 0) st_rel(&d_g_done[pid * FPAD], u);
        }
    }
}

// ---------------- launch ----------------
extern "C" void kernel_launch(void* const* d_in, const int* in_sizes, int n_in,
                              void* d_out, int out_size) {
    const float* batch = (const float*)d_in[0];
    const float* W_ih  = (const float*)d_in[1];
    const float* W_hh  = (const float*)d_in[2];
    const float* b_ih  = (const float*)d_in[3];
    const float* b_hh  = (const float*)d_in[4];
    float* out = (float*)d_out;

    const int smem = (SRED + 4 * 32 * 20) * 4;   // 33792 + 10240 = 44032 B
    cudaFuncSetAttribute(lstm2d_k, cudaFuncAttributeMaxDynamicSharedMemorySize, smem);

    init_k<<<8, 256>>>();
    xc_k<<<dim3(64, 16), 128>>>(batch, W_ih, b_ih, b_hh);
    lstm2d_k<<<GRIDSZ, THREADS, smem>>>(W_ih, W_hh, out);
}

// round 11
// speedup vs baseline: 2.7216x; 1.0469x over previous
#include <cuda_runtime.h>
#include <cuda_bf16.h>
#include <cuda_fp16.h>
#include <cstdint>

// ---------------- problem constants ----------------
#define TB      64          // batch
#define NCH     512         // hidden cells
#define TSTEPS  1024        // SY*SX
#define G4      2048        // 4*NCH gate columns
#define K_IH    560         // 48 + NCH
#define NSEQ    64          // sequential-worker CTAs (8 h-cols = 32 gate cols each)
#define NPRE    64          // pre-worker CTAs (32 contiguous gate cols each)
#define GRIDSZ  (NSEQ + NPRE)
#define THREADS 256         // 8 warps: wl=w&3 row-group, kh=w>>2 K-half
#define HSTRIDE ((size_t)TSTEPS * NCH)  // out batch-row stride (flat [t][n] view)
#define S_W     264         // smem words/col, fp16 pairs (==8 mod 32 -> conflict-free LDS.64)
#define S_X     48          // xc_k smem words/col (bf16 quads, K=48)
#define FPAD    32          // ints per flag: one 128B line each
#define SRED    (32 * S_W)  // word offset of reduction scratch
#define HQS     64          // h ring slots (8 MB total, L2-resident)

// ---------------- device scratch (static: allocation-free) ----------------
__device__ float d_G[(size_t)TSTEPS * TB * G4];        // gate pre-activations, 512 MB
__device__ uint4 d_Hq[(size_t)HQS * TB * 128];         // h ring: {hi2,hi2,lo2,lo2} per 4 cells
__device__ int   d_h_done[NSEQ * FPAD];
__device__ int   d_g_done[NPRE * FPAD];
__device__ int   d_l_done[NSEQ * FPAD];                // "seq started loading step t" stagger flags

// ---------------- bf16 helpers (xc_k only) ----------------
__device__ __forceinline__ uint32_t pack2b(float e0, float e1) {   // e0 -> low half
    uint32_t d;
    asm("cvt.rn.bf16x2.f32 %0, %1, %2;" : "=r"(d) : "f"(e1), "f"(e0));
    return d;
}
__device__ __forceinline__ uint32_t lo_resb(uint32_t hp, float e0, float e1) {
    float h0 = __uint_as_float(hp << 16);
    float h1 = __uint_as_float(hp & 0xFFFF0000u);
    return pack2b(e0 - h0, e1 - h1);
}
__device__ __forceinline__ void mma16b(float* c,
                                       uint32_t a0, uint32_t a1, uint32_t a2, uint32_t a3,
                                       uint32_t b0, uint32_t b1) {
    asm volatile(
        "mma.sync.aligned.m16n8k16.row.col.f32.bf16.bf16.f32 "
        "{%0,%1,%2,%3},{%4,%5,%6,%7},{%8,%9},{%0,%1,%2,%3};"
        : "+f"(c[0]), "+f"(c[1]), "+f"(c[2]), "+f"(c[3])
        : "r"(a0), "r"(a1), "r"(a2), "r"(a3), "r"(b0), "r"(b1));
}

// ---------------- fp16 helpers (main kernel) ----------------
__device__ __forceinline__ uint32_t pack2h(float e0, float e1) {   // e0 -> low half
    uint32_t d;
    asm("cvt.rn.f16x2.f32 %0, %1, %2;" : "=r"(d) : "f"(e1), "f"(e0));
    return d;
}
__device__ __forceinline__ uint32_t lo_resh(uint32_t hp, float e0, float e1) {
    __half2 h = *reinterpret_cast<__half2*>(&hp);
    float h0 = __half2float(__low2half(h));
    float h1 = __half2float(__high2half(h));
    return pack2h(e0 - h0, e1 - h1);
}
__device__ __forceinline__ void mma16h(float* c,
                                       uint32_t a0, uint32_t a1, uint32_t a2, uint32_t a3,
                                       uint32_t b0, uint32_t b1) {
    asm volatile(
        "mma.sync.aligned.m16n8k16.row.col.f32.f16.f16.f32 "
        "{%0,%1,%2,%3},{%4,%5,%6,%7},{%8,%9},{%0,%1,%2,%3};"
        : "+f"(c[0]), "+f"(c[1]), "+f"(c[2]), "+f"(c[3])
        : "r"(a0), "r"(a1), "r"(a2), "r"(a3), "r"(b0), "r"(b1));
}

__device__ __forceinline__ int ld_acq(const int* p) {
    int v;
    asm volatile("ld.acquire.gpu.global.b32 %0, [%1];" : "=r"(v) : "l"(p) : "memory");
    return v;
}
__device__ __forceinline__ void st_rel(int* p, int v) {
    asm volatile("st.release.gpu.global.b32 [%0], %1;" :: "l"(p), "r"(v) : "memory");
}
__device__ __forceinline__ uint4 ldcg4(const uint4* p) {
    uint4 v;
    asm volatile("ld.global.cg.v4.b32 {%0,%1,%2,%3}, [%4];"
                 : "=r"(v.x), "=r"(v.y), "=r"(v.z), "=r"(v.w) : "l"(p));
    return v;
}
__device__ __forceinline__ float sigm(float x)  { return 1.0f / (1.0f + __expf(-x)); }
__device__ __forceinline__ float tanh_f(float x){ return 1.0f - 2.0f / (__expf(2.0f * x) + 1.0f); }

// ---------------- init (graph-replay safe) ----------------
__global__ void init_k() {
    int i = blockIdx.x * blockDim.x + threadIdx.x;
    if (i < NSEQ * FPAD) { d_h_done[i] = -1; d_l_done[i] = -1; }
    if (i < NPRE * FPAD) d_g_done[i] = 31;   // G[0..31] have no h part: ready after xc_k
}

// ---------------- Xc precompute: G0[t] = bias + x_t @ W_ih[:, :48]^T (bf16 3-pass) ----------------
__global__ void __launch_bounds__(128)
xc_k(const float* __restrict__ batch, const float* __restrict__ W_ih,
     const float* __restrict__ b_ih, const float* __restrict__ b_hh) {
    __shared__ uint32_t sw[32 * S_X];
    const int tid = threadIdx.x;
    const int lane = tid & 31, w = tid >> 5;
    const int gid = lane >> 2, tig = lane & 3;
    const int row0 = w * 16 + gid, row1 = row0 + 8;
    const int gb = blockIdx.x * 32;

    for (int idx = tid; idx < 32 * 24; idx += 128) {
        int cl = idx / 24, k0 = (idx - cl * 24) * 2;
        float w0 = W_ih[(size_t)(gb + cl) * K_IH + k0];
        float w1 = W_ih[(size_t)(gb + cl) * K_IH + k0 + 1];
        uint32_t hi = pack2b(w0, w1);
        int kt = k0 >> 4, r = k0 & 15;
        int pos = cl * S_X + kt * 16 + (r >> 2) * 4 + ((r >> 1) & 1);
        sw[pos] = hi; sw[pos + 2] = lo_resb(hi, w0, w1);
    }
    __syncthreads();

    float bias[4][2];
#pragma unroll
    for (int nt = 0; nt < 4; nt++) {
        int g = gb + nt * 8 + tig * 2;
        bias[nt][0] = b_ih[g] + b_hh[g];
        bias[nt][1] = b_ih[g + 1] + b_hh[g + 1];
    }

    for (int us = 0; us < 64; us++) {
        const int u = blockIdx.y * 64 + us;
        const int i = u >> 5, j = u & 31;
        float acc[4][4];
#pragma unroll
        for (int nt = 0; nt < 4; nt++) {
            acc[nt][0] = bias[nt][0]; acc[nt][1] = bias[nt][1];
            acc[nt][2] = bias[nt][0]; acc[nt][3] = bias[nt][1];
        }
#pragma unroll
        for (int kt = 0; kt < 3; kt++) {       // c = kt, p = tig, q = 0..3
            float4 f0 = *(const float4*)&batch[(((size_t)row0 * 3 + kt) * 128 + i * 4 + tig) * 128 + j * 4];
            float4 f1 = *(const float4*)&batch[(((size_t)row1 * 3 + kt) * 128 + i * 4 + tig) * 128 + j * 4];
            uint32_t ah0 = pack2b(f0.x, f0.y), ah2 = pack2b(f0.z, f0.w);
            uint32_t ah1 = pack2b(f1.x, f1.y), ah3 = pack2b(f1.z, f1.w);
            uint32_t al0 = lo_resb(ah0, f0.x, f0.y), al2 = lo_resb(ah2, f0.z, f0.w);
            uint32_t al1 = lo_resb(ah1, f1.x, f1.y), al3 = lo_resb(ah3, f1.z, f1.w);
#pragma unroll
            for (int nt = 0; nt < 4; nt++) {
                const uint4 q = *(const uint4*)&sw[(nt * 8 + gid) * S_X + kt * 16 + tig * 4];
                mma16b(acc[nt], ah0, ah1, ah2, ah3, q.x, q.y);
                mma16b(acc[nt], ah0, ah1, ah2, ah3, q.z, q.w);
                mma16b(acc[nt], al0, al1, al2, al3, q.x, q.y);
            }
        }
        float* gp = d_G + (size_t)u * TB * G4;
#pragma unroll
        for (int nt = 0; nt < 4; nt++) {
            float* p0 = gp + (size_t)row0 * G4 + gb + nt * 8 + tig * 2;
            float* p1 = gp + (size_t)row1 * G4 + gb + nt * 8 + tig * 2;
            *(float2*)p0 = make_float2(acc[nt][0], acc[nt][1]);
            *(float2*)p1 = make_float2(acc[nt][2], acc[nt][3]);
        }
    }
}

// ---------------- persistent 2D-LSTM kernel (fp16 2-pass) ----------------
extern __shared__ uint32_t smw[];   // [0, 32*S_W): fp16 weights; [SRED, +2560): reduction

__global__ void __launch_bounds__(THREADS, 1)
lstm2d_k(const float* __restrict__ W_ih, const float* __restrict__ W_hh,
         float* __restrict__ out) {
    const int tid  = threadIdx.x;
    const int lane = tid & 31;
    const int w    = tid >> 5;
    const int wl   = w & 3;             // row group: batch rows [16wl, 16wl+16)
    const int kh   = w >> 2;            // K half: kt range [16kh, 16kh+16)
    const int gid  = lane >> 2;
    const int tig  = lane & 3;
    const int bid  = blockIdx.x;
    const int row0 = wl * 16 + gid;
    const int row1 = row0 + 8;
    const int ktb  = kh * 16;
    const bool seq = (bid < NSEQ);
    float* red = (float*)(smw + SRED);

    // ---- weights (K=512) -> smem fp16 pairs. seq: W_hh; pre: W_ih[:,48:560] ----
    {
        const int nb32 = seq ? bid * 8 : (bid - NSEQ) * 32;
        for (int idx = tid; idx < 32 * 256; idx += THREADS) {
            int cl = idx >> 8, k0 = (idx & 255) * 2;
            float w0, w1;
            if (seq) {
                int grow = (cl >> 3) * NCH + nb32 + (cl & 7);
                w0 = W_hh[(size_t)grow * NCH + k0];
                w1 = W_hh[(size_t)grow * NCH + k0 + 1];
            } else {
                w0 = W_ih[(size_t)(nb32 + cl) * K_IH + 48 + k0];
                w1 = W_ih[(size_t)(nb32 + cl) * K_IH + 48 + k0 + 1];
            }
            int kt = k0 >> 4, r = k0 & 15;
            smw[cl * S_W + kt * 8 + (r >> 2) * 2 + ((r >> 1) & 1)] = pack2h(w0, w1);
        }
        __syncthreads();
    }

    if (seq) {
        // ================= SEQUENTIAL WORKER =================
        const int nb = bid * 8;
        const int n0 = nb + tig * 2;
        float cst[4] = {0.f, 0.f, 0.f, 0.f};
        const int gdep = (tid < 4) ? (tid * 16 + (bid >> 2)) * FPAD : 0;

        float ga[4][4];
        if (kh == 0) {
            const float* gp = d_G;
#pragma unroll
            for (int gg = 0; gg < 4; gg++) {
                float2 v0 = __ldcg((const float2*)(gp + (size_t)row0 * G4 + gg * NCH + n0));
                float2 v1 = __ldcg((const float2*)(gp + (size_t)row1 * G4 + gg * NCH + n0));
                ga[gg][0] = v0.x; ga[gg][1] = v0.y; ga[gg][2] = v1.x; ga[gg][3] = v1.y;
            }
        }

        for (int t = 0; t < TSTEPS; t++) {
            const int tn = (t < TSTEPS - 1) ? t + 1 : TSTEPS - 1;
            // poll: g-flags one step AHEAD (enables G prefetch); h-flags for t-1
            if (tid < 4) { while (ld_acq(&d_g_done[gdep]) < tn) {} }
            else if (tid >= 64 && tid < 128 && t > 0) {
                while (ld_acq(&d_h_done[(tid - 64) * FPAD]) < t - 1) {}
            }
            __syncthreads();
            // stagger flag: this CTA is now issuing its h(t-1) loads
            if (tid == 0) st_rel(&d_l_done[bid * FPAD], t);

            float acc[4][4];
#pragma unroll
            for (int gg = 0; gg < 4; gg++) {
#pragma unroll
                for (int i = 0; i < 4; i++) acc[gg][i] = (kh == 0) ? ga[gg][i] : 0.f;
            }

            if (t > 0) {
                uint4 A0[16], A1[16];
                const size_t hs = (size_t)((t - 1) & (HQS - 1)) * TB;
                const uint4* pq0 = d_Hq + (hs + row0) * 128 + ktb * 4 + tig;
                const uint4* pq1 = d_Hq + (hs + row1) * 128 + ktb * 4 + tig;
#pragma unroll
                for (int kt = 0; kt < 16; kt++) { A0[kt] = ldcg4(pq0 + kt * 4); A1[kt] = ldcg4(pq1 + kt * 4); }
#pragma unroll
                for (int kt = 0; kt < 16; kt++) {
#pragma unroll
                    for (int gg = 0; gg < 4; gg++) {
                        const uint2 q = *(const uint2*)&smw[(gg * 8 + gid) * S_W + (ktb + kt) * 8 + tig * 2];
                        mma16h(acc[gg], A0[kt].x, A1[kt].x, A0[kt].y, A1[kt].y, q.x, q.y);  // hi*W
                        mma16h(acc[gg], A0[kt].z, A1[kt].z, A0[kt].w, A1[kt].w, q.x, q.y);  // lo*W
                    }
                }
            }
            if (kh == 0) {   // prefetch ga <- G[t+1] (after mma issue; hidden)
                const float* gp = d_G + (size_t)tn * TB * G4;
#pragma unroll
                for (int gg = 0; gg < 4; gg++) {
                    float2 v0 = __ldcg((const float2*)(gp + (size_t)row0 * G4 + gg * NCH + n0));
                    float2 v1 = __ldcg((const float2*)(gp + (size_t)row1 * G4 + gg * NCH + n0));
                    ga[gg][0] = v0.x; ga[gg][1] = v0.y; ga[gg][2] = v1.x; ga[gg][3] = v1.y;
                }
            }

            // K-half reduction: upper warps -> smem, lower warps add
            if (kh == 1) {
                float* rp = red + (wl * 32 + lane) * 20;
#pragma unroll
                for (int gg = 0; gg < 4; gg++)
                    *(float4*)(rp + gg * 4) = make_float4(acc[gg][0], acc[gg][1], acc[gg][2], acc[gg][3]);
            }
            __syncthreads();

            if (kh == 0) {
                const float* rp = red + (wl * 32 + lane) * 20;
#pragma unroll
                for (int gg = 0; gg < 4; gg++) {
                    float4 v = *(const float4*)(rp + gg * 4);
                    acc[gg][0] += v.x; acc[gg][1] += v.y; acc[gg][2] += v.z; acc[gg][3] += v.w;
                }

                // activations (i,f,g,o) + publish
                uint32_t hp[2], lp[2];
#pragma unroll
                for (int half = 0; half < 2; half++) {
                    const int pA = half * 2, pB = half * 2 + 1;
                    const int bb = (half == 0) ? row0 : row1;
                    float c0 = sigm(acc[1][pA]) * cst[pA] + sigm(acc[0][pA]) * tanh_f(acc[2][pA]);
                    float c1 = sigm(acc[1][pB]) * cst[pB] + sigm(acc[0][pB]) * tanh_f(acc[2][pB]);
                    cst[pA] = c0; cst[pB] = c1;
                    float h0 = sigm(acc[3][pA]) * tanh_f(c0);
                    float h1 = sigm(acc[3][pB]) * tanh_f(c1);
                    *(float2*)&out[(size_t)bb * HSTRIDE + (size_t)t * NCH + n0] = make_float2(h0, h1);
                    hp[half] = pack2h(h0, h1);
                    lp[half] = lo_resh(hp[half], h0, h1);
                }
                uint32_t hp0p = __shfl_xor_sync(0xffffffffu, hp[0], 1);
                uint32_t lp0p = __shfl_xor_sync(0xffffffffu, lp[0], 1);
                uint32_t hp1p = __shfl_xor_sync(0xffffffffu, hp[1], 1);
                uint32_t lp1p = __shfl_xor_sync(0xffffffffu, lp[1], 1);
                const int grp = (nb >> 2) + (tig >> 1);
                uint4 val; size_t rsel;
                if (tig & 1) { val = make_uint4(hp1p, hp[1], lp1p, lp[1]); rsel = row1; }
                else         { val = make_uint4(hp[0], hp0p, lp[0], lp0p); rsel = row0; }
                d_Hq[((size_t)(t & (HQS - 1)) * TB + rsel) * 128 + grp] = val;
            }
            __syncthreads();
            if (tid == 0) st_rel(&d_h_done[bid * FPAD], t);
        }
    } else {
        // ================= PRE-WORKER: G[u] = G0[u] + h_{u-32} @ W_ihh^T =================
        const int pid = bid - NSEQ;
        const int gb  = pid * 32;

        float ga[4][4];
        if (kh == 0) {
            const float* gp = d_G + (size_t)32 * TB * G4;
#pragma unroll
            for (int nt = 0; nt < 4; nt++) {
                float2 v0 = __ldcg((const float2*)(gp + (size_t)row0 * G4 + gb + nt * 8 + tig * 2));
                float2 v1 = __ldcg((const float2*)(gp + (size_t)row1 * G4 + gb + nt * 8 + tig * 2));
                ga[nt][0] = v0.x; ga[nt][1] = v0.y; ga[nt][2] = v1.x; ga[nt][3] = v1.y;
            }
        }

        for (int u = 32; u < TSTEPS; u++) {
            const int un = (u < TSTEPS - 1) ? u + 1 : TSTEPS - 1;
            // wait for h(u-32), and for seq step u-31 to have started its loads (burst stagger)
            if (tid < 64) { while (ld_acq(&d_h_done[tid * FPAD]) < u - 32) {} }
            else if (tid < 128) { while (ld_acq(&d_l_done[(tid - 64) * FPAD]) < u - 31) {} }
            __syncthreads();

            float acc[4][4];
#pragma unroll
            for (int nt = 0; nt < 4; nt++) {
#pragma unroll
                for (int i = 0; i < 4; i++) acc[nt][i] = (kh == 0) ? ga[nt][i] : 0.f;
            }

            {
                uint4 A0[16], A1[16];
                const size_t hs = (size_t)((u - 32) & (HQS - 1)) * TB;
                const uint4* pq0 = d_Hq + (hs + row0) * 128 + ktb * 4 + tig;
                const uint4* pq1 = d_Hq + (hs + row1) * 128 + ktb * 4 + tig;
#pragma unroll
                for (int kt = 0; kt < 16; kt++) { A0[kt] = ldcg4(pq0 + kt * 4); A1[kt] = ldcg4(pq1 + kt * 4); }
#pragma unroll
                for (int kt = 0; kt < 16; kt++) {
#pragma unroll
                    for (int nt = 0; nt < 4; nt++) {
                        const uint2 q = *(const uint2*)&smw[(nt * 8 + gid) * S_W + (ktb + kt) * 8 + tig * 2];
                        mma16h(acc[nt], A0[kt].x, A1[kt].x, A0[kt].y, A1[kt].y, q.x, q.y);
                        mma16h(acc[nt], A0[kt].z, A1[kt].z, A0[kt].w, A1[kt].w, q.x, q.y);
                    }
                }
            }
            if (kh == 0) {   // prefetch G0[u+1] (raw xc output; only this CTA updates it)
                const float* gp = d_G + (size_t)un * TB * G4;
#pragma unroll
                for (int nt = 0; nt < 4; nt++) {
                    float2 v0 = __ldcg((const float2*)(gp + (size_t)row0 * G4 + gb + nt * 8 + tig * 2));
                    float2 v1 = __ldcg((const float2*)(gp + (size_t)row1 * G4 + gb + nt * 8 + tig * 2));
                    ga[nt][0] = v0.x; ga[nt][1] = v0.y; ga[nt][2] = v1.x; ga[nt][3] = v1.y;
                }
            }

            if (kh == 1) {
                float* rp = red + (wl * 32 + lane) * 20;
#pragma unroll
                for (int nt = 0; nt < 4; nt++)
                    *(float4*)(rp + nt * 4) = make_float4(acc[nt][0], acc[nt][1], acc[nt][2], acc[nt][3]);
            }
            __syncthreads();

            if (kh == 0) {
                const float* rp = red + (wl * 32 + lane) * 20;
#pragma unroll
                for (int nt = 0; nt < 4; nt++) {
                    float4 v = *(const float4*)(rp + nt * 4);
                    acc[nt][0] += v.x; acc[nt][1] += v.y; acc[nt][2] += v.z; acc[nt][3] += v.w;
                }
                float* gw = d_G + (size_t)u * TB * G4;
#pragma unroll
                for (int nt = 0; nt < 4; nt++) {
                    float* p0 = gw + (size_t)row0 * G4 + gb + nt * 8 + tig * 2;
                    float* p1 = gw + (size_t)row1 * G4 + gb + nt * 8 + tig * 2;
                    *(float2*)p0 = make_float2(acc[nt][0], acc[nt][1]);
                    *(float2*)p1 = make_float2(acc[nt][2], acc[nt][3]);
                }
            }
            __syncthreads();
            if (tid == 0) st_rel(&d_g_done[pid * FPAD], u);
        }
    }
}

// ---------------- launch ----------------
extern "C" void kernel_launch(void* const* d_in, const int* in_sizes, int n_in,
                              void* d_out, int out_size) {
    const float* batch = (const float*)d_in[0];
    const float* W_ih  = (const float*)d_in[1];
    const float* W_hh  = (const float*)d_in[2];
    const float* b_ih  = (const float*)d_in[3];
    const float* b_hh  = (const float*)d_in[4];
    float* out = (float*)d_out;

    const int smem = (SRED + 4 * 32 * 20) * 4;   // 33792 + 10240 = 44032 B
    cudaFuncSetAttribute(lstm2d_k, cudaFuncAttributeMaxDynamicSharedMemorySize, smem);

    init_k<<<8, 256>>>();
    xc_k<<<dim3(64, 16), 128>>>(batch, W_ih, b_ih, b_hh);
    lstm2d_k<<<GRIDSZ, THREADS, smem>>>(W_ih, W_hh, out);
}